// round 3
// baseline (speedup 1.0000x reference)
#include <cuda_runtime.h>

#define NTOT   8192
#define DD     512
#define BHALF  4096
#define INV_T  2.0f
#define BK     16

// Scratch (device globals — no allocations allowed in kernel_launch)
__device__ float g_z[NTOT * DD];      // normalized embeddings (16 MB, L2-resident)
__device__ float g_pos[NTOT];         // positive-pair similarities
__device__ float g_part[64 * NTOT];   // per-slot row partial denom sums (2 MB)
__device__ float g_blk[64];           // per-block loss partials

__device__ __forceinline__ unsigned long long ffma2(unsigned long long a,
                                                    unsigned long long b,
                                                    unsigned long long c) {
    unsigned long long d;
    asm("fma.rn.f32x2 %0, %1, %2, %3;" : "=l"(d) : "l"(a), "l"(b), "l"(c));
    return d;
}

// ---------------- Kernel 1: L2-normalize rows of [polyline; c] ----------------
__global__ void knorm(const float* __restrict__ pe, const float* __restrict__ ce) {
    int row = blockIdx.x;
    const float* src = (row < BHALF) ? (pe + (size_t)row * DD)
                                     : (ce + (size_t)(row - BHALF) * DD);
    int t = threadIdx.x;  // 128 threads, 4 floats each
    float4 v = ((const float4*)src)[t];
    float ss = v.x * v.x + v.y * v.y + v.z * v.z + v.w * v.w;
#pragma unroll
    for (int o = 16; o > 0; o >>= 1) ss += __shfl_xor_sync(0xffffffffu, ss, o);
    __shared__ float ws[4];
    if ((t & 31) == 0) ws[t >> 5] = ss;
    __syncthreads();
    float tot = ws[0] + ws[1] + ws[2] + ws[3];
    float inv = 1.0f / fmaxf(sqrtf(tot), 1e-12f);
    v.x *= inv; v.y *= inv; v.z *= inv; v.w *= inv;
    ((float4*)(g_z + (size_t)row * DD))[t] = v;
}

// ------- Kernel 2: triangular tiled Z·Z^T with fused exp/rowsum epilogue -------
// Block (it, jt) with it <= jt computes S[a][b] = z_{it*128+a} . z_{jt*128+b}.
// Row-side sums -> slot jt of row-group it; col-side sums (it<jt) -> slot it of
// row-group jt. Slots per row-group are disjoint and cover 0..63 exactly.
__global__ __launch_bounds__(256, 2) void kgemm() {
    __shared__ float As[BK][256];     // duplicated: As[k][2m] = As[k][2m+1] = A[m][k]
    __shared__ float Bs[BK][128];
    __shared__ float red[128][17];    // padded reduction buffer

    const int it = blockIdx.y, jt = blockIdx.x;
    if (it > jt) return;              // upper triangle only

    const int tid = threadIdx.x;
    const int tx = tid & 15, ty = tid >> 4;

    const float* Ab = g_z + (size_t)(it * 128) * DD;
    const float* Bb = g_z + (size_t)(jt * 128) * DD;

    const int lr = tid >> 2;          // 0..63 (row within half-tile)
    const int lk = (tid & 3) * 4;     // 0,4,8,12 (k-quad)

    unsigned long long acc[8][4];
#pragma unroll
    for (int r = 0; r < 8; r++)
#pragma unroll
        for (int c = 0; c < 4; c++) acc[r][c] = 0ull;

    // register prefetch of first chunk
    float4 pa0 = *(const float4*)(Ab + (size_t)lr * DD + lk);
    float4 pa1 = *(const float4*)(Ab + (size_t)(lr + 64) * DD + lk);
    float4 pb0 = *(const float4*)(Bb + (size_t)lr * DD + lk);
    float4 pb1 = *(const float4*)(Bb + (size_t)(lr + 64) * DD + lk);

    for (int kb = 0; kb < DD; kb += BK) {
#pragma unroll
        for (int i = 0; i < 4; i++) {
            float a0 = ((const float*)&pa0)[i];
            float a1 = ((const float*)&pa1)[i];
            *(float2*)&As[lk + i][2 * lr]        = make_float2(a0, a0);
            *(float2*)&As[lk + i][2 * (lr + 64)] = make_float2(a1, a1);
            Bs[lk + i][lr]      = ((const float*)&pb0)[i];
            Bs[lk + i][lr + 64] = ((const float*)&pb1)[i];
        }
        __syncthreads();

        int kn = kb + BK;
        if (kn < DD) {  // prefetch next chunk; overlaps with compute below
            pa0 = *(const float4*)(Ab + (size_t)lr * DD + kn + lk);
            pa1 = *(const float4*)(Ab + (size_t)(lr + 64) * DD + kn + lk);
            pb0 = *(const float4*)(Bb + (size_t)lr * DD + kn + lk);
            pb1 = *(const float4*)(Bb + (size_t)(lr + 64) * DD + kn + lk);
        }

#pragma unroll
        for (int k = 0; k < BK; k++) {
            ulonglong2 a01 = *(const ulonglong2*)&As[k][ty * 16];
            ulonglong2 a23 = *(const ulonglong2*)&As[k][ty * 16 + 4];
            ulonglong2 a45 = *(const ulonglong2*)&As[k][ty * 16 + 8];
            ulonglong2 a67 = *(const ulonglong2*)&As[k][ty * 16 + 12];
            ulonglong2 b01 = *(const ulonglong2*)&Bs[k][tx * 8];
            ulonglong2 b23 = *(const ulonglong2*)&Bs[k][tx * 8 + 4];
            unsigned long long aa[8] = {a01.x, a01.y, a23.x, a23.y,
                                        a45.x, a45.y, a67.x, a67.y};
            unsigned long long bb[4] = {b01.x, b01.y, b23.x, b23.y};
#pragma unroll
            for (int r = 0; r < 8; r++)
#pragma unroll
                for (int c = 0; c < 4; c++)
                    acc[r][c] = ffma2(aa[r], bb[c], acc[r][c]);
        }
        __syncthreads();
    }

    // ---- epilogue: exp, positive capture, row & column sums ----
    const int i0 = it * 128 + ty * 8;
    const int j0 = jt * 128 + tx * 8;
    float rs[8], cs[8];
#pragma unroll
    for (int r = 0; r < 8; r++) { rs[r] = 0.0f; cs[r] = 0.0f; }

#pragma unroll
    for (int r = 0; r < 8; r++) {
        int gi = i0 + r;
#pragma unroll
        for (int c = 0; c < 4; c++) {
            float2 v = *(float2*)&acc[r][c];
            int gj = j0 + 2 * c;
            // element (gi, gj)
            if (gj == (gi ^ BHALF)) { g_pos[gi] = v.x; g_pos[gj] = v.x; }
            float e0 = (gj != gi) ? __expf(v.x * INV_T) : 0.0f;
            rs[r] += e0; cs[2 * c] += e0;
            // element (gi, gj+1)
            int gj1 = gj + 1;
            if (gj1 == (gi ^ BHALF)) { g_pos[gi] = v.y; g_pos[gj1] = v.y; }
            float e1 = (gj1 != gi) ? __expf(v.y * INV_T) : 0.0f;
            rs[r] += e1; cs[2 * c + 1] += e1;
        }
    }

    // row-side reduction across tx
#pragma unroll
    for (int r = 0; r < 8; r++) red[ty * 8 + r][tx] = rs[r];
    __syncthreads();
    if (tid < 128) {
        float s = 0.0f;
#pragma unroll
        for (int x = 0; x < 16; x++) s += red[tid][x];
        g_part[(size_t)jt * NTOT + it * 128 + tid] = s;
    }
    __syncthreads();

    // col-side reduction across ty (off-diagonal blocks only)
    if (it != jt) {
#pragma unroll
        for (int c = 0; c < 8; c++) red[tx * 8 + c][ty] = cs[c];
        __syncthreads();
        if (tid < 128) {
            float s = 0.0f;
#pragma unroll
            for (int x = 0; x < 16; x++) s += red[tid][x];
            g_part[(size_t)it * NTOT + jt * 128 + tid] = s;
        }
    }
}

// ---------------- Kernel 3: per-row loss, deterministic reduction ----------------
__global__ void kfin1() {
    int i = blockIdx.x * 128 + threadIdx.x;
    float d = 0.0f;
#pragma unroll 8
    for (int t = 0; t < 64; t++) d += g_part[(size_t)t * NTOT + i];
    float l = logf(d) - g_pos[i] * INV_T;
#pragma unroll
    for (int o = 16; o > 0; o >>= 1) l += __shfl_xor_sync(0xffffffffu, l, o);
    __shared__ float ws[4];
    if ((threadIdx.x & 31) == 0) ws[threadIdx.x >> 5] = l;
    __syncthreads();
    if (threadIdx.x == 0) g_blk[blockIdx.x] = ws[0] + ws[1] + ws[2] + ws[3];
}

__global__ void kfin2(float* out) {
    int t = threadIdx.x;  // 64
    float v = g_blk[t];
#pragma unroll
    for (int o = 16; o > 0; o >>= 1) v += __shfl_xor_sync(0xffffffffu, v, o);
    __shared__ float ws[2];
    if ((t & 31) == 0) ws[t >> 5] = v;
    __syncthreads();
    if (t == 0) out[0] = (ws[0] + ws[1]) / (float)NTOT;
}

extern "C" void kernel_launch(void* const* d_in, const int* in_sizes, int n_in,
                              void* d_out, int out_size) {
    const float* pe = (const float*)d_in[0];
    const float* ce = (const float*)d_in[1];
    knorm<<<NTOT, 128>>>(pe, ce);
    dim3 g(64, 64);
    kgemm<<<g, 256>>>();
    kfin1<<<64, 128>>>();
    kfin2<<<1, 64>>>((float*)d_out);
}

// round 6
// speedup vs baseline: 4.3332x; 4.3332x over previous
#include <cuda_runtime.h>
#include <cuda_bf16.h>
#include <cstdint>

#define NTOT   8192
#define DD     512
#define BHALF  4096
#define TILM   128
#define NCHUNK 8            // K=512 in chunks of 64 bf16 (128B rows, SW128-style xor)
#define NGRP   64           // 8192/128 row groups
#define SCALE  2.885390081777927f   // 2 * log2(e)

// ---- device scratch (no allocations allowed) ----
__device__ uint4  g_za[NTOT * 64];      // bf16 z * SCALE (8 MB), 64 uint4 per row
__device__ uint4  g_zb[NTOT * 64];      // bf16 z (8 MB)
__device__ float  g_pos[NTOT];
__device__ float  g_part[NGRP * NTOT];  // per-slot row partial denom sums (2 MB)
__device__ float  g_blk[64];

// dynamic smem layout (bytes)
#define OFF_A(b)   ((b) * 32768)            // A chunk buffer: 128 rows x 128B
#define OFF_B(b)   (16384 + (b) * 32768)    // B chunk buffer
#define OFF_REDR   65536                    // 128*4 floats
#define OFF_REDC   67584                    // 128*2 floats
#define SMEM_DYN   68608

__device__ __forceinline__ uint32_t smem_u32(const void* p) {
    uint32_t a;
    asm("{ .reg .u64 t; cvta.to.shared.u64 t, %1; cvt.u32.u64 %0, t; }" : "=r"(a) : "l"(p));
    return a;
}
__device__ __forceinline__ uint32_t swz(uint32_t off) {   // SW128-style xor on 16B granules
    return off ^ ((off >> 3) & 0x70);
}
__device__ __forceinline__ void cp16(uint32_t dst, const void* src) {
    asm volatile("cp.async.cg.shared.global [%0], [%1], 16;" :: "r"(dst), "l"(src));
}
__device__ __forceinline__ void ldsm4(uint32_t* r, uint32_t addr) {
    asm volatile("ldmatrix.sync.aligned.m8n8.x4.shared.b16 {%0,%1,%2,%3}, [%4];"
                 : "=r"(r[0]), "=r"(r[1]), "=r"(r[2]), "=r"(r[3]) : "r"(addr));
}
__device__ __forceinline__ void mma16816(float* c, const uint32_t* a,
                                         uint32_t b0, uint32_t b1) {
    asm volatile(
        "mma.sync.aligned.m16n8k16.row.col.f32.bf16.bf16.f32 "
        "{%0,%1,%2,%3}, {%4,%5,%6,%7}, {%8,%9}, {%0,%1,%2,%3};"
        : "+f"(c[0]), "+f"(c[1]), "+f"(c[2]), "+f"(c[3])
        : "r"(a[0]), "r"(a[1]), "r"(a[2]), "r"(a[3]), "r"(b0), "r"(b1));
}

// ---------------- Kernel 1: normalize rows, emit bf16 (plain + pre-scaled) ----------------
__global__ void knorm(const float* __restrict__ pe, const float* __restrict__ ce) {
    int row = blockIdx.x;
    const float* src = (row < BHALF) ? (pe + (size_t)row * DD)
                                     : (ce + (size_t)(row - BHALF) * DD);
    int t = threadIdx.x;  // 128 threads, 4 floats each
    float4 v = ((const float4*)src)[t];
    float ss = v.x * v.x + v.y * v.y + v.z * v.z + v.w * v.w;
#pragma unroll
    for (int o = 16; o > 0; o >>= 1) ss += __shfl_xor_sync(0xffffffffu, ss, o);
    __shared__ float ws[4];
    if ((t & 31) == 0) ws[t >> 5] = ss;
    __syncthreads();
    float inv = 1.0f / fmaxf(sqrtf(ws[0] + ws[1] + ws[2] + ws[3]), 1e-12f);
    float x0 = v.x * inv, x1 = v.y * inv, x2 = v.z * inv, x3 = v.w * inv;

    __nv_bfloat162 b0 = __floats2bfloat162_rn(x0, x1);
    __nv_bfloat162 b1 = __floats2bfloat162_rn(x2, x3);
    uint2 pb;
    pb.x = *(const unsigned int*)&b0;
    pb.y = *(const unsigned int*)&b1;
    ((uint2*)g_zb)[(size_t)row * 128 + t] = pb;

    __nv_bfloat162 a0 = __floats2bfloat162_rn(x0 * SCALE, x1 * SCALE);
    __nv_bfloat162 a1 = __floats2bfloat162_rn(x2 * SCALE, x3 * SCALE);
    uint2 pa;
    pa.x = *(const unsigned int*)&a0;
    pa.y = *(const unsigned int*)&a1;
    ((uint2*)g_za)[(size_t)row * 128 + t] = pa;
}

// ---------------- Kernel 2: positive pairs, exact fp32 from raw inputs ----------------
__global__ void kpos(const float* __restrict__ pe, const float* __restrict__ ce) {
    int i = blockIdx.x;      // 0..4095
    int t = threadIdx.x;     // 128
    float4 a = ((const float4*)(pe + (size_t)i * DD))[t];
    float4 b = ((const float4*)(ce + (size_t)i * DD))[t];
    float sa = a.x * a.x + a.y * a.y + a.z * a.z + a.w * a.w;
    float sb = b.x * b.x + b.y * b.y + b.z * b.z + b.w * b.w;
    float sc = a.x * b.x + a.y * b.y + a.z * b.z + a.w * b.w;
#pragma unroll
    for (int o = 16; o > 0; o >>= 1) {
        sa += __shfl_xor_sync(0xffffffffu, sa, o);
        sb += __shfl_xor_sync(0xffffffffu, sb, o);
        sc += __shfl_xor_sync(0xffffffffu, sc, o);
    }
    __shared__ float wa[4], wb[4], wc[4];
    if ((t & 31) == 0) { wa[t >> 5] = sa; wb[t >> 5] = sb; wc[t >> 5] = sc; }
    __syncthreads();
    if (t == 0) {
        float na = fmaxf(sqrtf(wa[0] + wa[1] + wa[2] + wa[3]), 1e-12f);
        float nb = fmaxf(sqrtf(wb[0] + wb[1] + wb[2] + wb[3]), 1e-12f);
        float d = (wc[0] + wc[1] + wc[2] + wc[3]) / (na * nb);
        g_pos[i] = d;
        g_pos[i + BHALF] = d;
    }
}

// ------- Kernel 3: triangular bf16 mma.sync GEMM (128x128) + fused exp epilogue -------
// Block (it,jt), it<=jt: Y[a][b] = za_{it*128+a} . zb_{jt*128+b}  (= sim * 2log2e).
// exp2(Y) summed: row-side -> slot jt of group it; col-side (it<jt) -> slot it of group jt.
__global__ __launch_bounds__(256, 2) void kgemm() {
    const int it = blockIdx.y, jt = blockIdx.x;
    if (it > jt) return;

    extern __shared__ char dsm[];
    const uint32_t sbase = smem_u32(dsm);
    const int tid = threadIdx.x;
    const int wid = tid >> 5, lid = tid & 31;
    const int wm = wid >> 2, wn = wid & 3;      // warp grid 2(M) x 4(N); warp tile 64x32

    const uint4* gA = g_za + (size_t)(it * TILM) * 64;
    const uint4* gB = g_zb + (size_t)(jt * TILM) * 64;

    float acc[4][4][4];
#pragma unroll
    for (int mi = 0; mi < 4; mi++)
#pragma unroll
        for (int n = 0; n < 4; n++)
#pragma unroll
            for (int f = 0; f < 4; f++) acc[mi][n][f] = 0.0f;

    // async chunk loader: threads 0-127 -> A rows, 128-255 -> B rows; 128B per row
    auto load_chunk = [&](int ch, int bf) {
        int r = tid & 127;
        const uint4* src = ((tid < 128) ? gA : gB) + (size_t)r * 64 + ch * 8;
        uint32_t dbase = sbase + ((tid < 128) ? OFF_A(bf) : OFF_B(bf));
        uint32_t rb = (uint32_t)r * 128;
#pragma unroll
        for (int i = 0; i < 8; i++)
            cp16(dbase + swz(rb + i * 16), src + i);
        asm volatile("cp.async.commit_group;" ::: "memory");
    };

    auto compute_chunk = [&](int bf) {
        uint32_t abase = sbase + OFF_A(bf);
        uint32_t bbase = sbase + OFF_B(bf);
#pragma unroll
        for (int s = 0; s < 4; s++) {           // 4 x k16 per 64-col chunk
            uint32_t kb = s * 32;               // byte offset of k16 slice
            uint32_t afr[4][4], bfr[2][4];
#pragma unroll
            for (int mi = 0; mi < 4; mi++) {
                uint32_t row = wm * 64 + mi * 16 + (lid & 15);
                ldsm4(afr[mi], abase + swz(row * 128 + kb + (lid >> 4) * 16));
            }
#pragma unroll
            for (int nq = 0; nq < 2; nq++) {
                uint32_t row = wn * 32 + nq * 16 + (lid & 15);
                ldsm4(bfr[nq], bbase + swz(row * 128 + kb + (lid >> 4) * 16));
            }
            // bfr[nq] regs: [0]=b0(n low8) [1]=b0(n high8) [2]=b1(low) [3]=b1(high)
#pragma unroll
            for (int mi = 0; mi < 4; mi++)
#pragma unroll
                for (int nq = 0; nq < 2; nq++)
#pragma unroll
                    for (int nh = 0; nh < 2; nh++)
                        mma16816(acc[mi][nq * 2 + nh], afr[mi],
                                 bfr[nq][nh], bfr[nq][nh + 2]);
        }
    };

    load_chunk(0, 0);
    for (int c = 0; c < NCHUNK; c++) {
        if (c < NCHUNK - 1) {
            load_chunk(c + 1, (c + 1) & 1);
            asm volatile("cp.async.wait_group 1;" ::: "memory");
        } else {
            asm volatile("cp.async.wait_group 0;" ::: "memory");
        }
        __syncthreads();
        compute_chunk(c & 1);
        __syncthreads();
    }

    // ---- epilogue: exp2 (arg pre-scaled by 2log2e), branch-free ----
#pragma unroll
    for (int mi = 0; mi < 4; mi++)
#pragma unroll
        for (int n = 0; n < 4; n++)
#pragma unroll
            for (int f = 0; f < 4; f++) {
                float e;
                asm("ex2.approx.f32 %0, %1;" : "=f"(e) : "f"(acc[mi][n][f]));
                acc[mi][n][f] = e;
            }

    float* redr = (float*)(dsm + OFF_REDR);   // [128][4] row partials per n-warp
    float* redc = (float*)(dsm + OFF_REDC);   // [128][2] col partials per m-warp

    // row sums: c frag rows = lid/4 (+8); cols (lid%4)*2 (+1)
#pragma unroll
    for (int mi = 0; mi < 4; mi++)
#pragma unroll
        for (int rh = 0; rh < 2; rh++) {
            float rs = 0.0f;
#pragma unroll
            for (int n = 0; n < 4; n++)
                rs += acc[mi][n][rh * 2] + acc[mi][n][rh * 2 + 1];
            rs += __shfl_xor_sync(0xffffffffu, rs, 1);
            rs += __shfl_xor_sync(0xffffffffu, rs, 2);
            if ((lid & 3) == 0) {
                int row = wm * 64 + mi * 16 + rh * 8 + (lid >> 2);
                redr[row * 4 + wn] = rs;
            }
        }
    // col sums
#pragma unroll
    for (int n = 0; n < 4; n++)
#pragma unroll
        for (int cc = 0; cc < 2; cc++) {
            float cs = 0.0f;
#pragma unroll
            for (int mi = 0; mi < 4; mi++)
                cs += acc[mi][n][cc] + acc[mi][n][2 + cc];
            cs += __shfl_xor_sync(0xffffffffu, cs, 4);
            cs += __shfl_xor_sync(0xffffffffu, cs, 8);
            cs += __shfl_xor_sync(0xffffffffu, cs, 16);
            if ((lid >> 2) == 0) {
                int col = wn * 32 + n * 8 + (lid & 3) * 2 + cc;
                redc[col * 2 + wm] = cs;
            }
        }
    __syncthreads();

    if (tid < 128) {
        float rs = redr[tid * 4] + redr[tid * 4 + 1] + redr[tid * 4 + 2] + redr[tid * 4 + 3];
        g_part[(size_t)jt * NTOT + it * TILM + tid] = rs;              // row side: slot jt
        if (it != jt) {
            float cs = redc[tid * 2] + redc[tid * 2 + 1];
            g_part[(size_t)it * NTOT + jt * TILM + tid] = cs;          // col side: slot it
        }
    }
}

// ---------------- Kernel 4: per-row loss, deterministic reduction ----------------
__global__ void kfin1() {
    int i = blockIdx.x * 128 + threadIdx.x;
    float d = 0.0f;
#pragma unroll 8
    for (int t = 0; t < NGRP; t++) d += g_part[(size_t)t * NTOT + i];
    d -= 7.3890561f;                       // remove diagonal term exp(2*||z||^2) ~ e^2
    float l = logf(d) - g_pos[i] * 2.0f;   // 1/T = 2
#pragma unroll
    for (int o = 16; o > 0; o >>= 1) l += __shfl_xor_sync(0xffffffffu, l, o);
    __shared__ float ws[4];
    if ((threadIdx.x & 31) == 0) ws[threadIdx.x >> 5] = l;
    __syncthreads();
    if (threadIdx.x == 0) g_blk[blockIdx.x] = ws[0] + ws[1] + ws[2] + ws[3];
}

__global__ void kfin2(float* out) {
    int t = threadIdx.x;  // 64
    float v = g_blk[t];
#pragma unroll
    for (int o = 16; o > 0; o >>= 1) v += __shfl_xor_sync(0xffffffffu, v, o);
    __shared__ float ws[2];
    if ((t & 31) == 0) ws[t >> 5] = v;
    __syncthreads();
    if (t == 0) out[0] = (ws[0] + ws[1]) / (float)NTOT;
}

extern "C" void kernel_launch(void* const* d_in, const int* in_sizes, int n_in,
                              void* d_out, int out_size) {
    const float* pe = (const float*)d_in[0];
    const float* ce = (const float*)d_in[1];
    cudaFuncSetAttribute(kgemm, cudaFuncAttributeMaxDynamicSharedMemorySize, SMEM_DYN);
    knorm<<<NTOT, 128>>>(pe, ce);
    kpos<<<BHALF, 128>>>(pe, ce);
    dim3 g(NGRP, NGRP);
    kgemm<<<g, 256, SMEM_DYN>>>();
    kfin1<<<64, 128>>>();
    kfin2<<<1, 64>>>((float*)d_out);
}

// round 8
// speedup vs baseline: 5.8447x; 1.3488x over previous
#include <cuda_runtime.h>
#include <cstdint>

#define NTOT   8192
#define DD     512
#define BHALF  4096
#define TILM   128
#define NCHUNK 4            // K=512 fp8 in chunks of 128 (128B rows)
#define NGRP   64           // 8192/128 row groups
#define SCALE  2.885390081777927f   // 2 * log2(e)

// ---- device scratch (no allocations allowed) ----
__device__ uint4  g_za[NTOT * 32];      // fp8 z * SCALE (4 MB), 32 uint4 per row
__device__ uint4  g_zb[NTOT * 32];      // fp8 z (4 MB)
__device__ float  g_pos[NTOT];
__device__ float  g_part[NGRP * NTOT];  // per-slot row partial denom sums (2 MB)
__device__ float  g_blk[256];

// dynamic smem layout (bytes)
#define OFF_A(b)   ((b) * 32768)            // A chunk buffer: 128 rows x 128B
#define OFF_B(b)   (16384 + (b) * 32768)    // B chunk buffer
#define OFF_REDR   65536                    // 128*4 floats
#define OFF_REDC   67584                    // 128*2 floats
#define SMEM_DYN   68608

__device__ __forceinline__ uint32_t smem_u32(const void* p) {
    uint32_t a;
    asm("{ .reg .u64 t; cvta.to.shared.u64 t, %1; cvt.u32.u64 %0, t; }" : "=r"(a) : "l"(p));
    return a;
}
__device__ __forceinline__ uint32_t swz(uint32_t off) {   // SW128-style xor on 16B granules
    return off ^ ((off >> 3) & 0x70);
}
__device__ __forceinline__ void cp16(uint32_t dst, const void* src) {
    asm volatile("cp.async.cg.shared.global [%0], [%1], 16;" :: "r"(dst), "l"(src));
}
__device__ __forceinline__ void ldsm4(uint32_t* r, uint32_t addr) {
    asm volatile("ldmatrix.sync.aligned.m8n8.x4.shared.b16 {%0,%1,%2,%3}, [%4];"
                 : "=r"(r[0]), "=r"(r[1]), "=r"(r[2]), "=r"(r[3]) : "r"(addr));
}
__device__ __forceinline__ void mma16832(float* c, const uint32_t* a,
                                         uint32_t b0, uint32_t b1) {
    asm volatile(
        "mma.sync.aligned.m16n8k32.row.col.f32.e4m3.e4m3.f32 "
        "{%0,%1,%2,%3}, {%4,%5,%6,%7}, {%8,%9}, {%0,%1,%2,%3};"
        : "+f"(c[0]), "+f"(c[1]), "+f"(c[2]), "+f"(c[3])
        : "r"(a[0]), "r"(a[1]), "r"(a[2]), "r"(a[3]), "r"(b0), "r"(b1));
}
__device__ __forceinline__ uint32_t pack4_e4m3(float x0, float x1, float x2, float x3) {
    uint16_t lo, hi;   // cvt packs: high byte = first operand, low byte = second
    asm("cvt.rn.satfinite.e4m3x2.f32 %0, %1, %2;" : "=h"(lo) : "f"(x1), "f"(x0));
    asm("cvt.rn.satfinite.e4m3x2.f32 %0, %1, %2;" : "=h"(hi) : "f"(x3), "f"(x2));
    return (uint32_t)lo | ((uint32_t)hi << 16);
}

// ---- Kernel 1: fused normalize (fp8 emit, plain+scaled) + exact fp32 positives ----
// One block per pair i: threads 0-127 handle pe[i], 128-255 handle ce[i].
__global__ void kprep(const float* __restrict__ pe, const float* __restrict__ ce) {
    int i = blockIdx.x;
    int t = threadIdx.x;
    int half = t >> 7, u = t & 127;
    const float* rowp = half ? (ce + (size_t)i * DD) : (pe + (size_t)i * DD);
    float4 v = ((const float4*)rowp)[u];
    float ss = v.x * v.x + v.y * v.y + v.z * v.z + v.w * v.w;
#pragma unroll
    for (int o = 16; o > 0; o >>= 1) ss += __shfl_xor_sync(0xffffffffu, ss, o);
    __shared__ float wss[8], wsc[4];
    if ((t & 31) == 0) wss[t >> 5] = ss;

    if (half == 0) {   // cross-dot (second read of ce hits L2/DRAM once total)
        float4 w = ((const float4*)(ce + (size_t)i * DD))[u];
        float sc = v.x * w.x + v.y * w.y + v.z * w.z + v.w * w.w;
#pragma unroll
        for (int o = 16; o > 0; o >>= 1) sc += __shfl_xor_sync(0xffffffffu, sc, o);
        if ((t & 31) == 0) wsc[t >> 5] = sc;
    }
    __syncthreads();
    float na2 = wss[0] + wss[1] + wss[2] + wss[3];
    float nb2 = wss[4] + wss[5] + wss[6] + wss[7];
    float inv = 1.0f / fmaxf(sqrtf(half ? nb2 : na2), 1e-12f);
    float x0 = v.x * inv, x1 = v.y * inv, x2 = v.z * inv, x3 = v.w * inv;

    int row = half ? (i + BHALF) : i;
    ((uint32_t*)g_zb)[(size_t)row * 128 + u] = pack4_e4m3(x0, x1, x2, x3);
    ((uint32_t*)g_za)[(size_t)row * 128 + u] =
        pack4_e4m3(x0 * SCALE, x1 * SCALE, x2 * SCALE, x3 * SCALE);

    if (t == 0) {
        float na = fmaxf(sqrtf(na2), 1e-12f);
        float nb = fmaxf(sqrtf(nb2), 1e-12f);
        float d = (wsc[0] + wsc[1] + wsc[2] + wsc[3]) / (na * nb);
        g_pos[i] = d;
        g_pos[i + BHALF] = d;
    }
}

// ------- Kernel 2: triangular fp8 mma.sync GEMM (128x128) + fused exp epilogue -------
// Block (it,jt), it<=jt: Y[a][b] = za_{it*128+a} . zb_{jt*128+b}  (= sim * 2log2e).
// exp2(Y) summed: row-side -> slot jt of group it; col-side (it<jt) -> slot it of group jt.
__global__ __launch_bounds__(256, 2) void kgemm() {
    const int it = blockIdx.y, jt = blockIdx.x;
    if (it > jt) return;

    extern __shared__ char dsm[];
    const uint32_t sbase = smem_u32(dsm);
    const int tid = threadIdx.x;
    const int wid = tid >> 5, lid = tid & 31;
    const int wm = wid >> 2, wn = wid & 3;      // warp grid 2(M) x 4(N); warp tile 64x32

    const uint4* gA = g_za + (size_t)(it * TILM) * 32;   // 32 uint4 per 512B row
    const uint4* gB = g_zb + (size_t)(jt * TILM) * 32;

    float acc[4][4][4];
#pragma unroll
    for (int mi = 0; mi < 4; mi++)
#pragma unroll
        for (int n = 0; n < 4; n++)
#pragma unroll
            for (int f = 0; f < 4; f++) acc[mi][n][f] = 0.0f;

    // async chunk loader: threads 0-127 -> A rows, 128-255 -> B rows; 128B per row/chunk
    auto load_chunk = [&](int ch, int bf) {
        int r = tid & 127;
        const uint4* src = ((tid < 128) ? gA : gB) + (size_t)r * 32 + ch * 8;
        uint32_t dbase = sbase + ((tid < 128) ? OFF_A(bf) : OFF_B(bf));
        uint32_t rb = (uint32_t)r * 128;
#pragma unroll
        for (int i = 0; i < 8; i++)
            cp16(dbase + swz(rb + i * 16), src + i);
        asm volatile("cp.async.commit_group;" ::: "memory");
    };

    auto compute_chunk = [&](int bf) {
        uint32_t abase = sbase + OFF_A(bf);
        uint32_t bbase = sbase + OFF_B(bf);
#pragma unroll
        for (int s = 0; s < 4; s++) {           // 4 x k32 slices per 128-fp8 chunk
            uint32_t kb = s * 32;               // byte offset of k32 slice
            uint32_t afr[4][4], bfr[2][4];
#pragma unroll
            for (int mi = 0; mi < 4; mi++) {
                uint32_t row = wm * 64 + mi * 16 + (lid & 15);
                ldsm4(afr[mi], abase + swz(row * 128 + kb + (lid >> 4) * 16));
            }
#pragma unroll
            for (int nq = 0; nq < 2; nq++) {
                uint32_t row = wn * 32 + nq * 16 + (lid & 15);
                ldsm4(bfr[nq], bbase + swz(row * 128 + kb + (lid >> 4) * 16));
            }
            // bfr[nq] regs: [0]=n low8,k0-15  [1]=n high8,k0-15  [2]=low,k16-31  [3]=high,k16-31
#pragma unroll
            for (int mi = 0; mi < 4; mi++)
#pragma unroll
                for (int nq = 0; nq < 2; nq++)
#pragma unroll
                    for (int nh = 0; nh < 2; nh++)
                        mma16832(acc[mi][nq * 2 + nh], afr[mi],
                                 bfr[nq][nh], bfr[nq][nh + 2]);
        }
    };

    load_chunk(0, 0);
    for (int c = 0; c < NCHUNK; c++) {
        if (c < NCHUNK - 1) {
            load_chunk(c + 1, (c + 1) & 1);
            asm volatile("cp.async.wait_group 1;" ::: "memory");
        } else {
            asm volatile("cp.async.wait_group 0;" ::: "memory");
        }
        __syncthreads();
        compute_chunk(c & 1);
        __syncthreads();
    }

    // ---- epilogue: exp2 (arg pre-scaled by 2log2e), branch-free ----
#pragma unroll
    for (int mi = 0; mi < 4; mi++)
#pragma unroll
        for (int n = 0; n < 4; n++)
#pragma unroll
            for (int f = 0; f < 4; f++) {
                float e;
                asm("ex2.approx.f32 %0, %1;" : "=f"(e) : "f"(acc[mi][n][f]));
                acc[mi][n][f] = e;
            }

    float* redr = (float*)(dsm + OFF_REDR);   // [128][4] row partials per n-warp
    float* redc = (float*)(dsm + OFF_REDC);   // [128][2] col partials per m-warp

    // row sums: c-frag rows = lid/4 (+8); cols (lid%4)*2 (+1)
#pragma unroll
    for (int mi = 0; mi < 4; mi++)
#pragma unroll
        for (int rh = 0; rh < 2; rh++) {
            float rs = 0.0f;
#pragma unroll
            for (int n = 0; n < 4; n++)
                rs += acc[mi][n][rh * 2] + acc[mi][n][rh * 2 + 1];
            rs += __shfl_xor_sync(0xffffffffu, rs, 1);
            rs += __shfl_xor_sync(0xffffffffu, rs, 2);
            if ((lid & 3) == 0) {
                int row = wm * 64 + mi * 16 + rh * 8 + (lid >> 2);
                redr[row * 4 + wn] = rs;
            }
        }
    // col sums
#pragma unroll
    for (int n = 0; n < 4; n++)
#pragma unroll
        for (int cc = 0; cc < 2; cc++) {
            float cs = 0.0f;
#pragma unroll
            for (int mi = 0; mi < 4; mi++)
                cs += acc[mi][n][cc] + acc[mi][n][2 + cc];
            cs += __shfl_xor_sync(0xffffffffu, cs, 4);
            cs += __shfl_xor_sync(0xffffffffu, cs, 8);
            cs += __shfl_xor_sync(0xffffffffu, cs, 16);
            if ((lid >> 2) == 0) {
                int col = wn * 32 + n * 8 + (lid & 3) * 2 + cc;
                redc[col * 2 + wm] = cs;
            }
        }
    __syncthreads();

    if (tid < 128) {
        float rs = redr[tid * 4] + redr[tid * 4 + 1] + redr[tid * 4 + 2] + redr[tid * 4 + 3];
        g_part[(size_t)jt * NTOT + it * TILM + tid] = rs;              // row side: slot jt
        if (it != jt) {
            float cs = redc[tid * 2] + redc[tid * 2 + 1];
            g_part[(size_t)it * NTOT + jt * TILM + tid] = cs;          // col side: slot it
        }
    }
}

// ---------------- Kernel 3: per-row loss, wide deterministic reduction ----------------
__global__ void kfin1() {
    int t = threadIdx.x;               // 256
    int r = t & 31, seg = t >> 5;      // 8 segments x 32 rows
    int row = blockIdx.x * 32 + r;
    float d = 0.0f;
#pragma unroll
    for (int s = 0; s < 8; s++)
        d += g_part[(size_t)(seg * 8 + s) * NTOT + row];
    __shared__ float red[8][33];
    red[seg][r] = d;
    __syncthreads();
    if (t < 32) {
        float dd = 0.0f;
#pragma unroll
        for (int s = 0; s < 8; s++) dd += red[s][t];
        dd -= 7.3890561f;              // remove diagonal term exp2(SCALE*||z||^2) ~ e^2
        int row2 = blockIdx.x * 32 + t;
        float l = logf(dd) - g_pos[row2] * 2.0f;   // 1/T = 2
#pragma unroll
        for (int o = 16; o > 0; o >>= 1) l += __shfl_xor_sync(0xffffffffu, l, o);
        if (t == 0) g_blk[blockIdx.x] = l;
    }
}

__global__ void kfin2(float* out) {
    int t = threadIdx.x;  // 256
    float v = g_blk[t];
#pragma unroll
    for (int o = 16; o > 0; o >>= 1) v += __shfl_xor_sync(0xffffffffu, v, o);
    __shared__ float ws[8];
    if ((t & 31) == 0) ws[t >> 5] = v;
    __syncthreads();
    if (t == 0) {
        float s = 0.0f;
#pragma unroll
        for (int w = 0; w < 8; w++) s += ws[w];
        out[0] = s / (float)NTOT;
    }
}

extern "C" void kernel_launch(void* const* d_in, const int* in_sizes, int n_in,
                              void* d_out, int out_size) {
    const float* pe = (const float*)d_in[0];
    const float* ce = (const float*)d_in[1];
    cudaFuncSetAttribute(kgemm, cudaFuncAttributeMaxDynamicSharedMemorySize, SMEM_DYN);
    kprep<<<BHALF, 256>>>(pe, ce);
    dim3 g(NGRP, NGRP);
    kgemm<<<g, 256, SMEM_DYN>>>();
    kfin1<<<256, 256>>>();
    kfin2<<<1, 256>>>((float*)d_out);
}

// round 9
// speedup vs baseline: 8.5498x; 1.4628x over previous
#include <cuda_runtime.h>
#include <cstdint>

#define NTOT   8192
#define DD     512
#define BHALF  4096
#define TILM   128
#define NCHUNK 4            // K=512 fp8 in chunks of 128B rows
#define NGRP   64           // 8192/128 row groups
#define NBLK   (NGRP * (NGRP + 1) / 2)   // 2080 triangular blocks
#define SCALE  2.885390081777927f        // 2 * log2(e)

// ---- device scratch (no allocations allowed) ----
// chunk-major pre-swizzled fp8: [group 64][chunk 4][16KB swizzled block]
__device__ uint4  g_za[NTOT * 32];      // z * SCALE (4 MB)
__device__ uint4  g_zb[NTOT * 32];      // z (4 MB)
__device__ float  g_pos[NTOT];
__device__ float  g_part[NGRP * NTOT];  // per-slot row partial denom sums (2 MB)
__device__ float  g_blk[256];

// dynamic smem layout (bytes, after 1024-alignment)
#define OFF_A(b)   ((b) * 16384)            // A chunk buffers (2 x 16KB)
#define OFF_B(b)   (32768 + (b) * 16384)    // B chunk buffers (2 x 16KB)
#define OFF_REDR   65536                    // 128*4 floats
#define OFF_REDC   67584                    // 128*2 floats
#define OFF_MBAR   68608                    // 2 mbarriers
#define SMEM_DYN   69760                    // incl. 1KB alignment slack

__device__ __forceinline__ uint32_t smem_u32(const void* p) {
    uint32_t a;
    asm("{ .reg .u64 t; cvta.to.shared.u64 t, %1; cvt.u32.u64 %0, t; }" : "=r"(a) : "l"(p));
    return a;
}
__device__ __forceinline__ uint32_t swz(uint32_t off) {   // SW128 xor on 16B granules
    return off ^ ((off >> 3) & 0x70);
}
__device__ __forceinline__ void ldsm4(uint32_t* r, uint32_t addr) {
    asm volatile("ldmatrix.sync.aligned.m8n8.x4.shared.b16 {%0,%1,%2,%3}, [%4];"
                 : "=r"(r[0]), "=r"(r[1]), "=r"(r[2]), "=r"(r[3]) : "r"(addr));
}
__device__ __forceinline__ void mma16832(float* c, const uint32_t* a,
                                         uint32_t b0, uint32_t b1) {
    asm volatile(
        "mma.sync.aligned.m16n8k32.row.col.f32.e4m3.e4m3.f32 "
        "{%0,%1,%2,%3}, {%4,%5,%6,%7}, {%8,%9}, {%0,%1,%2,%3};"
        : "+f"(c[0]), "+f"(c[1]), "+f"(c[2]), "+f"(c[3])
        : "r"(a[0]), "r"(a[1]), "r"(a[2]), "r"(a[3]), "r"(b0), "r"(b1));
}
__device__ __forceinline__ uint32_t pack4_e4m3(float x0, float x1, float x2, float x3) {
    uint16_t lo, hi;   // cvt packs: high byte = first operand, low byte = second
    asm("cvt.rn.satfinite.e4m3x2.f32 %0, %1, %2;" : "=h"(lo) : "f"(x1), "f"(x0));
    asm("cvt.rn.satfinite.e4m3x2.f32 %0, %1, %2;" : "=h"(hi) : "f"(x3), "f"(x2));
    return (uint32_t)lo | ((uint32_t)hi << 16);
}
__device__ __forceinline__ void bulk_ld(uint32_t dst, const void* src, uint32_t bytes,
                                        uint32_t mbar) {
    asm volatile("cp.async.bulk.shared::cluster.global.mbarrier::complete_tx::bytes "
                 "[%0], [%1], %2, [%3];"
                 :: "r"(dst), "l"(src), "r"(bytes), "r"(mbar) : "memory");
}

#define MBAR_WAIT(mbar, parity) do {                                           \
    uint32_t _m = (mbar), _p = (parity), _done;                                \
    asm volatile("{ .reg .pred p; mbarrier.try_wait.parity.acquire.cta.shared::cta.b64 p, [%1], %2; selp.b32 %0,1,0,p; }" \
                 : "=r"(_done) : "r"(_m), "r"(_p) : "memory");                 \
    if (!_done) {                                                              \
        asm volatile("{ .reg .pred P1; WL_%=: mbarrier.try_wait.parity.acquire.cta.shared::cta.b64 P1, [%0], %1, 0x989680; @P1 bra.uni WD_%=; bra.uni WL_%=; WD_%=: }" \
                     :: "r"(_m), "r"(_p) : "memory");                          \
    }                                                                          \
} while (0)

// ---- Kernel 1: fused normalize (fp8 emit, chunk-major pre-swizzled) + exact positives ----
// One block per pair i: threads 0-127 handle pe[i], 128-255 handle ce[i].
__global__ void kprep(const float* __restrict__ pe, const float* __restrict__ ce) {
    int i = blockIdx.x;
    int t = threadIdx.x;
    int half = t >> 7, u = t & 127;
    const float* rowp = half ? (ce + (size_t)i * DD) : (pe + (size_t)i * DD);
    float4 v = ((const float4*)rowp)[u];
    float ss = v.x * v.x + v.y * v.y + v.z * v.z + v.w * v.w;
#pragma unroll
    for (int o = 16; o > 0; o >>= 1) ss += __shfl_xor_sync(0xffffffffu, ss, o);
    __shared__ float wss[8], wsc[4];
    if ((t & 31) == 0) wss[t >> 5] = ss;

    if (half == 0) {   // cross-dot for exact fp32 positives
        float4 w = ((const float4*)(ce + (size_t)i * DD))[u];
        float sc = v.x * w.x + v.y * w.y + v.z * w.z + v.w * w.w;
#pragma unroll
        for (int o = 16; o > 0; o >>= 1) sc += __shfl_xor_sync(0xffffffffu, sc, o);
        if ((t & 31) == 0) wsc[t >> 5] = sc;
    }
    __syncthreads();
    float na2 = wss[0] + wss[1] + wss[2] + wss[3];
    float nb2 = wss[4] + wss[5] + wss[6] + wss[7];
    float inv = 1.0f / fmaxf(sqrtf(half ? nb2 : na2), 1e-12f);
    float x0 = v.x * inv, x1 = v.y * inv, x2 = v.z * inv, x3 = v.w * inv;

    int row = half ? (i + BHALF) : i;
    // chunk-major, pre-swizzled byte address
    size_t base = ((size_t)(row >> 7) * 4 + (u >> 5)) * 16384;
    uint32_t rel = (uint32_t)(((row & 127) << 7) | ((u << 2) & 127));
    uint32_t off = swz(rel);
    *(uint32_t*)((char*)g_zb + base + off) = pack4_e4m3(x0, x1, x2, x3);
    *(uint32_t*)((char*)g_za + base + off) =
        pack4_e4m3(x0 * SCALE, x1 * SCALE, x2 * SCALE, x3 * SCALE);

    if (t == 0) {
        float na = fmaxf(sqrtf(na2), 1e-12f);
        float nb = fmaxf(sqrtf(nb2), 1e-12f);
        float d = (wsc[0] + wsc[1] + wsc[2] + wsc[3]) / (na * nb);
        g_pos[i] = d;
        g_pos[i + BHALF] = d;
    }
}

// ------- Kernel 2: triangular fp8 mma.sync GEMM (128x128) + fused exp epilogue -------
// 1D grid of 2080 blocks -> (it,jt), it<=jt. Y = za_i . zb_j = sim * 2log2e.
// exp2(Y) summed: row-side -> slot jt of group it; col-side (it<jt) -> slot it of group jt.
__global__ __launch_bounds__(256, 2) void kgemm() {
    int bid = blockIdx.x;
    int jt = (int)((sqrtf(8.0f * (float)bid + 1.0f) - 1.0f) * 0.5f);
    while ((jt + 1) * (jt + 2) / 2 <= bid) jt++;
    while (jt * (jt + 1) / 2 > bid) jt--;
    const int it = bid - jt * (jt + 1) / 2;    // it <= jt guaranteed

    extern __shared__ char dsm_raw[];
    const uint32_t rawb = smem_u32(dsm_raw);
    const uint32_t sbase = (rawb + 1023) & ~1023u;   // 1024-align for swizzle banks
    char* dsm = dsm_raw + (sbase - rawb);

    const int tid = threadIdx.x;
    const int wid = tid >> 5, lid = tid & 31;
    const int wm = wid >> 2, wn = wid & 3;      // warp grid 2(M) x 4(N); warp tile 64x32

    const char* gA = (const char*)g_za + (size_t)it * 65536;   // 4 chunks x 16KB
    const char* gB = (const char*)g_zb + (size_t)jt * 65536;

    if (tid == 0) {
        asm volatile("mbarrier.init.shared.b64 [%0], %1;"
                     :: "r"(sbase + OFF_MBAR), "r"(1u) : "memory");
        asm volatile("mbarrier.init.shared.b64 [%0], %1;"
                     :: "r"(sbase + OFF_MBAR + 8), "r"(1u) : "memory");
        asm volatile("fence.proxy.async.shared::cta;" ::: "memory");
    }
    __syncthreads();

    float acc[4][4][4];
#pragma unroll
    for (int mi = 0; mi < 4; mi++)
#pragma unroll
        for (int n = 0; n < 4; n++)
#pragma unroll
            for (int f = 0; f < 4; f++) acc[mi][n][f] = 0.0f;

    // bulk chunk issue (thread 0): A+B 16KB each into buffer bf, tx=32KB
    auto issue_chunk = [&](int ch, int bf) {
        if (tid == 0) {
            uint32_t mb = sbase + OFF_MBAR + bf * 8;
            asm volatile("mbarrier.arrive.expect_tx.shared.b64 _, [%0], %1;"
                         :: "r"(mb), "r"(32768u) : "memory");
            bulk_ld(sbase + OFF_A(bf), gA + ch * 16384, 16384, mb);
            bulk_ld(sbase + OFF_B(bf), gB + ch * 16384, 16384, mb);
        }
    };

    auto compute_chunk = [&](int bf) {
        uint32_t abase = sbase + OFF_A(bf);
        uint32_t bbase = sbase + OFF_B(bf);
#pragma unroll
        for (int s = 0; s < 4; s++) {           // 4 x k32 slices per 128B chunk
            uint32_t kb = s * 32;
            uint32_t afr[4][4], bfr[2][4];
#pragma unroll
            for (int mi = 0; mi < 4; mi++) {
                uint32_t row = wm * 64 + mi * 16 + (lid & 15);
                ldsm4(afr[mi], abase + swz(row * 128 + kb + (lid >> 4) * 16));
            }
#pragma unroll
            for (int nq = 0; nq < 2; nq++) {
                uint32_t row = wn * 32 + nq * 16 + (lid & 15);
                ldsm4(bfr[nq], bbase + swz(row * 128 + kb + (lid >> 4) * 16));
            }
#pragma unroll
            for (int mi = 0; mi < 4; mi++)
#pragma unroll
                for (int nq = 0; nq < 2; nq++)
#pragma unroll
                    for (int nh = 0; nh < 2; nh++)
                        mma16832(acc[mi][nq * 2 + nh], afr[mi],
                                 bfr[nq][nh], bfr[nq][nh + 2]);
        }
    };

    issue_chunk(0, 0);
    for (int c = 0; c < NCHUNK; c++) {
        if (c < NCHUNK - 1) issue_chunk(c + 1, (c + 1) & 1);
        MBAR_WAIT(sbase + OFF_MBAR + (c & 1) * 8, (c >> 1) & 1);
        compute_chunk(c & 1);
        __syncthreads();   // all warps done before this buffer is re-issued
    }

    // ---- epilogue: exp2 (arg pre-scaled by 2log2e), branch-free ----
#pragma unroll
    for (int mi = 0; mi < 4; mi++)
#pragma unroll
        for (int n = 0; n < 4; n++)
#pragma unroll
            for (int f = 0; f < 4; f++) {
                float e;
                asm("ex2.approx.f32 %0, %1;" : "=f"(e) : "f"(acc[mi][n][f]));
                acc[mi][n][f] = e;
            }

    float* redr = (float*)(dsm + OFF_REDR);   // [128][4] row partials per n-warp
    float* redc = (float*)(dsm + OFF_REDC);   // [128][2] col partials per m-warp

    // row sums: c-frag rows = lid/4 (+8); cols (lid%4)*2 (+1)
#pragma unroll
    for (int mi = 0; mi < 4; mi++)
#pragma unroll
        for (int rh = 0; rh < 2; rh++) {
            float rs = 0.0f;
#pragma unroll
            for (int n = 0; n < 4; n++)
                rs += acc[mi][n][rh * 2] + acc[mi][n][rh * 2 + 1];
            rs += __shfl_xor_sync(0xffffffffu, rs, 1);
            rs += __shfl_xor_sync(0xffffffffu, rs, 2);
            if ((lid & 3) == 0) {
                int row = wm * 64 + mi * 16 + rh * 8 + (lid >> 2);
                redr[row * 4 + wn] = rs;
            }
        }
    // col sums
#pragma unroll
    for (int n = 0; n < 4; n++)
#pragma unroll
        for (int cc = 0; cc < 2; cc++) {
            float cs = 0.0f;
#pragma unroll
            for (int mi = 0; mi < 4; mi++)
                cs += acc[mi][n][cc] + acc[mi][n][2 + cc];
            cs += __shfl_xor_sync(0xffffffffu, cs, 4);
            cs += __shfl_xor_sync(0xffffffffu, cs, 8);
            cs += __shfl_xor_sync(0xffffffffu, cs, 16);
            if ((lid >> 2) == 0) {
                int col = wn * 32 + n * 8 + (lid & 3) * 2 + cc;
                redc[col * 2 + wm] = cs;
            }
        }
    __syncthreads();

    if (tid < 128) {
        float rs = redr[tid * 4] + redr[tid * 4 + 1] + redr[tid * 4 + 2] + redr[tid * 4 + 3];
        g_part[(size_t)jt * NTOT + it * TILM + tid] = rs;              // row side: slot jt
        if (it != jt) {
            float cs = redc[tid * 2] + redc[tid * 2 + 1];
            g_part[(size_t)it * NTOT + jt * TILM + tid] = cs;          // col side: slot it
        }
    }
}

// ---------------- Kernel 3: per-row loss, wide deterministic reduction ----------------
__global__ void kfin1() {
    int t = threadIdx.x;               // 256
    int r = t & 31, seg = t >> 5;      // 8 segments x 32 rows
    int row = blockIdx.x * 32 + r;
    float d = 0.0f;
#pragma unroll
    for (int s = 0; s < 8; s++)
        d += g_part[(size_t)(seg * 8 + s) * NTOT + row];
    __shared__ float red[8][33];
    red[seg][r] = d;
    __syncthreads();
    if (t < 32) {
        float dd = 0.0f;
#pragma unroll
        for (int s = 0; s < 8; s++) dd += red[s][t];
        dd -= 7.3890561f;              // remove diagonal term exp(2) exactly
        int row2 = blockIdx.x * 32 + t;
        float l = logf(dd) - g_pos[row2] * 2.0f;   // 1/T = 2
#pragma unroll
        for (int o = 16; o > 0; o >>= 1) l += __shfl_xor_sync(0xffffffffu, l, o);
        if (t == 0) g_blk[blockIdx.x] = l;
    }
}

__global__ void kfin2(float* out) {
    int t = threadIdx.x;  // 256
    float v = g_blk[t];
#pragma unroll
    for (int o = 16; o > 0; o >>= 1) v += __shfl_xor_sync(0xffffffffu, v, o);
    __shared__ float ws[8];
    if ((t & 31) == 0) ws[t >> 5] = v;
    __syncthreads();
    if (t == 0) {
        float s = 0.0f;
#pragma unroll
        for (int w = 0; w < 8; w++) s += ws[w];
        out[0] = s / (float)NTOT;
    }
}

extern "C" void kernel_launch(void* const* d_in, const int* in_sizes, int n_in,
                              void* d_out, int out_size) {
    const float* pe = (const float*)d_in[0];
    const float* ce = (const float*)d_in[1];
    cudaFuncSetAttribute(kgemm, cudaFuncAttributeMaxDynamicSharedMemorySize, SMEM_DYN);
    kprep<<<BHALF, 256>>>(pe, ce);
    kgemm<<<NBLK, 256, SMEM_DYN>>>();
    kfin1<<<256, 256>>>();
    kfin2<<<1, 256>>>((float*)d_out);
}

// round 10
// speedup vs baseline: 8.8799x; 1.0386x over previous
#include <cuda_runtime.h>
#include <cuda_fp16.h>
#include <cstdint>

#define NTOT   8192
#define DD     512
#define BHALF  4096
#define TILM   128
#define NCHUNK 4            // K=512 fp8 in chunks of 128B rows
#define NGRP   64           // 8192/128 row groups
#define NBLK   (NGRP * (NGRP + 1) / 2)   // 2080 triangular tiles
#define PGRID  296          // persistent grid: 2 CTAs/SM x 148 SMs
#define SCALE  2.885390081777927f        // 2 * log2(e)

// ---- device scratch (no allocations allowed) ----
// chunk-major pre-swizzled fp8: [group 64][chunk 4][16KB swizzled block]
__device__ uint4  g_za[NTOT * 32];      // z * SCALE (4 MB)
__device__ uint4  g_zb[NTOT * 32];      // z (4 MB)
__device__ float  g_pos[NTOT];
__device__ float  g_part[NGRP * NTOT];  // per-slot row partial denom sums (2 MB)
__device__ float  g_blk[256];
__device__ int    g_cnt;                // last-block-done counter (self-resetting)

// dynamic smem layout (bytes, after 1024-alignment)
#define OFF_A(b)   ((b) * 16384)            // A chunk buffers (2 x 16KB)
#define OFF_B(b)   (32768 + (b) * 16384)    // B chunk buffers (2 x 16KB)
#define OFF_REDR   65536                    // 128*4 floats
#define OFF_REDC   67584                    // 128*2 floats
#define OFF_MBAR   68608                    // 2 mbarriers
#define SMEM_DYN   69760                    // incl. 1KB alignment slack

__device__ __forceinline__ uint32_t smem_u32(const void* p) {
    uint32_t a;
    asm("{ .reg .u64 t; cvta.to.shared.u64 t, %1; cvt.u32.u64 %0, t; }" : "=r"(a) : "l"(p));
    return a;
}
__device__ __forceinline__ uint32_t swz(uint32_t off) {   // SW128 xor on 16B granules
    return off ^ ((off >> 3) & 0x70);
}
__device__ __forceinline__ void ldsm4(uint32_t* r, uint32_t addr) {
    asm volatile("ldmatrix.sync.aligned.m8n8.x4.shared.b16 {%0,%1,%2,%3}, [%4];"
                 : "=r"(r[0]), "=r"(r[1]), "=r"(r[2]), "=r"(r[3]) : "r"(addr));
}
// fp8 e4m3 mma with fp16 accumulators (2 packed c-regs)
__device__ __forceinline__ void mma16832h(uint32_t* c, const uint32_t* a,
                                          uint32_t b0, uint32_t b1) {
    asm volatile(
        "mma.sync.aligned.m16n8k32.row.col.f16.e4m3.e4m3.f16 "
        "{%0,%1}, {%2,%3,%4,%5}, {%6,%7}, {%0,%1};"
        : "+r"(c[0]), "+r"(c[1])
        : "r"(a[0]), "r"(a[1]), "r"(a[2]), "r"(a[3]), "r"(b0), "r"(b1));
}
__device__ __forceinline__ uint32_t pack4_e4m3(float x0, float x1, float x2, float x3) {
    uint16_t lo, hi;   // cvt packs: high byte = first operand, low byte = second
    asm("cvt.rn.satfinite.e4m3x2.f32 %0, %1, %2;" : "=h"(lo) : "f"(x1), "f"(x0));
    asm("cvt.rn.satfinite.e4m3x2.f32 %0, %1, %2;" : "=h"(hi) : "f"(x3), "f"(x2));
    return (uint32_t)lo | ((uint32_t)hi << 16);
}
__device__ __forceinline__ void bulk_ld(uint32_t dst, const void* src, uint32_t bytes,
                                        uint32_t mbar) {
    asm volatile("cp.async.bulk.shared::cluster.global.mbarrier::complete_tx::bytes "
                 "[%0], [%1], %2, [%3];"
                 :: "r"(dst), "l"(src), "r"(bytes), "r"(mbar) : "memory");
}

#define MBAR_WAIT(mbar, parity) do {                                           \
    uint32_t _m = (mbar), _p = (parity), _done;                                \
    asm volatile("{ .reg .pred p; mbarrier.try_wait.parity.acquire.cta.shared::cta.b64 p, [%1], %2; selp.b32 %0,1,0,p; }" \
                 : "=r"(_done) : "r"(_m), "r"(_p) : "memory");                 \
    if (!_done) {                                                              \
        asm volatile("{ .reg .pred P1; WL_%=: mbarrier.try_wait.parity.acquire.cta.shared::cta.b64 P1, [%0], %1, 0x989680; @P1 bra.uni WD_%=; bra.uni WL_%=; WD_%=: }" \
                     :: "r"(_m), "r"(_p) : "memory");                          \
    }                                                                          \
} while (0)

// ---- Kernel 1: fused normalize (fp8 emit, chunk-major pre-swizzled) + exact positives ----
__global__ void kprep(const float* __restrict__ pe, const float* __restrict__ ce) {
    int i = blockIdx.x;
    int t = threadIdx.x;
    int half = t >> 7, u = t & 127;
    const float* rowp = half ? (ce + (size_t)i * DD) : (pe + (size_t)i * DD);
    float4 v = ((const float4*)rowp)[u];
    float ss = v.x * v.x + v.y * v.y + v.z * v.z + v.w * v.w;
#pragma unroll
    for (int o = 16; o > 0; o >>= 1) ss += __shfl_xor_sync(0xffffffffu, ss, o);
    __shared__ float wss[8], wsc[4];
    if ((t & 31) == 0) wss[t >> 5] = ss;

    if (half == 0) {   // cross-dot for exact fp32 positives
        float4 w = ((const float4*)(ce + (size_t)i * DD))[u];
        float sc = v.x * w.x + v.y * w.y + v.z * w.z + v.w * w.w;
#pragma unroll
        for (int o = 16; o > 0; o >>= 1) sc += __shfl_xor_sync(0xffffffffu, sc, o);
        if ((t & 31) == 0) wsc[t >> 5] = sc;
    }
    __syncthreads();
    float na2 = wss[0] + wss[1] + wss[2] + wss[3];
    float nb2 = wss[4] + wss[5] + wss[6] + wss[7];
    float inv = 1.0f / fmaxf(sqrtf(half ? nb2 : na2), 1e-12f);
    float x0 = v.x * inv, x1 = v.y * inv, x2 = v.z * inv, x3 = v.w * inv;

    int row = half ? (i + BHALF) : i;
    size_t base = ((size_t)(row >> 7) * 4 + (u >> 5)) * 16384;   // chunk-major
    uint32_t off = swz((uint32_t)(((row & 127) << 7) | ((u << 2) & 127)));
    *(uint32_t*)((char*)g_zb + base + off) = pack4_e4m3(x0, x1, x2, x3);
    *(uint32_t*)((char*)g_za + base + off) =
        pack4_e4m3(x0 * SCALE, x1 * SCALE, x2 * SCALE, x3 * SCALE);

    if (t == 0) {
        float na = fmaxf(sqrtf(na2), 1e-12f);
        float nb = fmaxf(sqrtf(nb2), 1e-12f);
        float d = (wsc[0] + wsc[1] + wsc[2] + wsc[3]) / (na * nb);
        g_pos[i] = d;
        g_pos[i + BHALF] = d;
    }
}

__device__ __forceinline__ void decode_tri(int bid, int& it, int& jt) {
    jt = (int)((sqrtf(8.0f * (float)bid + 1.0f) - 1.0f) * 0.5f);
    while ((jt + 1) * (jt + 2) / 2 <= bid) jt++;
    while (jt * (jt + 1) / 2 > bid) jt--;
    it = bid - jt * (jt + 1) / 2;
}

// ------- Kernel 2: persistent triangular fp8 mma (fp16 acc) + fused exp epilogue -------
__global__ __launch_bounds__(256, 2) void kgemm() {
    extern __shared__ char dsm_raw[];
    const uint32_t rawb = smem_u32(dsm_raw);
    const uint32_t sbase = (rawb + 1023) & ~1023u;
    char* dsm = dsm_raw + (sbase - rawb);

    const int tid = threadIdx.x;
    const int wid = tid >> 5, lid = tid & 31;
    const int wm = wid >> 2, wn = wid & 3;      // warp grid 2(M) x 4(N); warp tile 64x32

    if (tid == 0) {
        asm volatile("mbarrier.init.shared.b64 [%0], %1;"
                     :: "r"(sbase + OFF_MBAR), "r"(1u) : "memory");
        asm volatile("mbarrier.init.shared.b64 [%0], %1;"
                     :: "r"(sbase + OFF_MBAR + 8), "r"(1u) : "memory");
        asm volatile("fence.proxy.async.shared::cta;" ::: "memory");
    }
    __syncthreads();

    auto issue = [&](const char* A, const char* B, int ch, int bf) {
        if (tid == 0) {
            uint32_t mb = sbase + OFF_MBAR + bf * 8;
            asm volatile("mbarrier.arrive.expect_tx.shared.b64 _, [%0], %1;"
                         :: "r"(mb), "r"(32768u) : "memory");
            bulk_ld(sbase + OFF_A(bf), A + ch * 16384, 16384, mb);
            bulk_ld(sbase + OFF_B(bf), B + ch * 16384, 16384, mb);
        }
    };

    int w8[2] = {0, 0};     // per-buffer completed-wait counters (phase tracking)
    int bid = blockIdx.x;
    if (bid >= NBLK) return;
    int it, jt;
    decode_tri(bid, it, jt);
    const char* gA = (const char*)g_za + (size_t)it * 65536;
    const char* gB = (const char*)g_zb + (size_t)jt * 65536;
    issue(gA, gB, 0, 0);

    while (true) {
        uint32_t acc[4][4][2];
#pragma unroll
        for (int mi = 0; mi < 4; mi++)
#pragma unroll
            for (int n = 0; n < 4; n++) { acc[mi][n][0] = 0u; acc[mi][n][1] = 0u; }

        int nbid = bid + PGRID;
        int it2 = 0, jt2 = 0;
        const char *gA2 = nullptr, *gB2 = nullptr;

        for (int c = 0; c < NCHUNK; c++) {
            if (c < NCHUNK - 1) {
                issue(gA, gB, c + 1, (c + 1) & 1);
            } else if (nbid < NBLK) {      // prefetch next tile's chunk0 into free buf0
                decode_tri(nbid, it2, jt2);
                gA2 = (const char*)g_za + (size_t)it2 * 65536;
                gB2 = (const char*)g_zb + (size_t)jt2 * 65536;
                issue(gA2, gB2, 0, 0);
            }
            int bf = c & 1;
            MBAR_WAIT(sbase + OFF_MBAR + bf * 8, w8[bf] & 1);
            w8[bf]++;
            uint32_t abase = sbase + OFF_A(bf);
            uint32_t bbase = sbase + OFF_B(bf);
#pragma unroll
            for (int s = 0; s < 4; s++) {       // 4 x k32 slices per 128B chunk
                uint32_t kb = s * 32;
                uint32_t afr[4][4], bfr[2][4];
#pragma unroll
                for (int mi = 0; mi < 4; mi++) {
                    uint32_t row = wm * 64 + mi * 16 + (lid & 15);
                    ldsm4(afr[mi], abase + swz(row * 128 + kb + (lid >> 4) * 16));
                }
#pragma unroll
                for (int nq = 0; nq < 2; nq++) {
                    uint32_t row = wn * 32 + nq * 16 + (lid & 15);
                    ldsm4(bfr[nq], bbase + swz(row * 128 + kb + (lid >> 4) * 16));
                }
#pragma unroll
                for (int mi = 0; mi < 4; mi++)
#pragma unroll
                    for (int nq = 0; nq < 2; nq++)
#pragma unroll
                        for (int nh = 0; nh < 2; nh++)
                            mma16832h(acc[mi][nq * 2 + nh], afr[mi],
                                      bfr[nq][nh], bfr[nq][nh + 2]);
            }
            __syncthreads();   // all warps done before buffer reuse
        }

        // ---- epilogue: unpack fp16, exp2 (pre-scaled arg), row+col sums ----
        float* redr = (float*)(dsm + OFF_REDR);   // [128][4]
        float* redc = (float*)(dsm + OFF_REDC);   // [128][2]
        float ef[4][4][4];
#pragma unroll
        for (int mi = 0; mi < 4; mi++)
#pragma unroll
            for (int n = 0; n < 4; n++) {
                float2 lo = __half22float2(*(__half2*)&acc[mi][n][0]);
                float2 hi = __half22float2(*(__half2*)&acc[mi][n][1]);
                float y[4] = {lo.x, lo.y, hi.x, hi.y};
#pragma unroll
                for (int f = 0; f < 4; f++) {
                    float e;
                    asm("ex2.approx.f32 %0, %1;" : "=f"(e) : "f"(y[f]));
                    ef[mi][n][f] = e;
                }
            }
        // row sums: c-frag rows = lid/4 (+8); cols (lid%4)*2 (+1)
#pragma unroll
        for (int mi = 0; mi < 4; mi++)
#pragma unroll
            for (int rh = 0; rh < 2; rh++) {
                float rs = 0.0f;
#pragma unroll
                for (int n = 0; n < 4; n++)
                    rs += ef[mi][n][rh * 2] + ef[mi][n][rh * 2 + 1];
                rs += __shfl_xor_sync(0xffffffffu, rs, 1);
                rs += __shfl_xor_sync(0xffffffffu, rs, 2);
                if ((lid & 3) == 0)
                    redr[(wm * 64 + mi * 16 + rh * 8 + (lid >> 2)) * 4 + wn] = rs;
            }
        // col sums
#pragma unroll
        for (int n = 0; n < 4; n++)
#pragma unroll
            for (int cc = 0; cc < 2; cc++) {
                float cs = 0.0f;
#pragma unroll
                for (int mi = 0; mi < 4; mi++)
                    cs += ef[mi][n][cc] + ef[mi][n][2 + cc];
                cs += __shfl_xor_sync(0xffffffffu, cs, 4);
                cs += __shfl_xor_sync(0xffffffffu, cs, 8);
                cs += __shfl_xor_sync(0xffffffffu, cs, 16);
                if ((lid >> 2) == 0)
                    redc[(wn * 32 + n * 8 + (lid & 3) * 2 + cc) * 2 + wm] = cs;
            }
        __syncthreads();

        if (tid < 128) {
            float rs = redr[tid * 4] + redr[tid * 4 + 1]
                     + redr[tid * 4 + 2] + redr[tid * 4 + 3];
            g_part[(size_t)jt * NTOT + it * TILM + tid] = rs;          // row side: slot jt
            if (it != jt) {
                float cs = redc[tid * 2] + redc[tid * 2 + 1];
                g_part[(size_t)it * NTOT + jt * TILM + tid] = cs;      // col side: slot it
            }
        }
        __syncthreads();   // redr/redc free before next tile's epilogue

        if (nbid >= NBLK) break;
        bid = nbid; it = it2; jt = jt2; gA = gA2; gB = gB2;
    }
}

// ---- Kernel 3: per-row loss + fused deterministic final reduction ----
__global__ void kfin1(float* out) {
    int t = threadIdx.x;               // 256
    int r = t & 31, seg = t >> 5;      // 8 segments x 32 rows
    int row = blockIdx.x * 32 + r;
    float d = 0.0f;
#pragma unroll
    for (int s = 0; s < 8; s++)
        d += g_part[(size_t)(seg * 8 + s) * NTOT + row];
    __shared__ float red[8][33];
    red[seg][r] = d;
    __syncthreads();
    if (t < 32) {
        float dd = 0.0f;
#pragma unroll
        for (int s = 0; s < 8; s++) dd += red[s][t];
        dd -= 7.3890561f;              // remove diagonal term exp(2)
        int row2 = blockIdx.x * 32 + t;
        float l = logf(dd) - g_pos[row2] * 2.0f;   // 1/T = 2
#pragma unroll
        for (int o = 16; o > 0; o >>= 1) l += __shfl_xor_sync(0xffffffffu, l, o);
        if (t == 0) g_blk[blockIdx.x] = l;
    }
    // last-block-done final sum (deterministic: fixed-order summation)
    __shared__ int is_last;
    __threadfence();
    __syncthreads();
    if (t == 0) is_last = (atomicAdd(&g_cnt, 1) == 255);
    __syncthreads();
    if (is_last) {
        float v = g_blk[t];
#pragma unroll
        for (int o = 16; o > 0; o >>= 1) v += __shfl_xor_sync(0xffffffffu, v, o);
        __shared__ float ws[8];
        if ((t & 31) == 0) ws[t >> 5] = v;
        __syncthreads();
        if (t == 0) {
            float s = 0.0f;
#pragma unroll
            for (int w = 0; w < 8; w++) s += ws[w];
            out[0] = s / (float)NTOT;
            g_cnt = 0;                 // reset for next graph replay
        }
    }
}

extern "C" void kernel_launch(void* const* d_in, const int* in_sizes, int n_in,
                              void* d_out, int out_size) {
    const float* pe = (const float*)d_in[0];
    const float* ce = (const float*)d_in[1];
    cudaFuncSetAttribute(kgemm, cudaFuncAttributeMaxDynamicSharedMemorySize, SMEM_DYN);
    kprep<<<BHALF, 256>>>(pe, ce);
    kgemm<<<PGRID, 256, SMEM_DYN>>>();
    kfin1<<<256, 256>>>((float*)d_out);
}